// round 10
// baseline (speedup 1.0000x reference)
#include <cuda_runtime.h>
#include <cstdint>

#define D 512
#define HW (D * D)            // 262144 = 2^18
#define NB 32                 // batch
#define IMG_ELEMS ((size_t)NB * 3 * HW)
#define LO 0.001f
#define HI 510.999f           // D - 1.001
#define NBLOCKS 16384         // 32 batch * 32 x-tiles(16 rows) * 16 y-tiles(32 cols)

__device__ __align__(16) float g_partials[NBLOCKS];

// select element j (0..3) of a float4
__device__ __forceinline__ float sel4(float4 V, int j) {
    float a = (j & 1) ? V.y : V.x;
    float b = (j & 1) ? V.w : V.z;
    return (j & 2) ? b : a;
}
// select element j+1 (valid for j in 0..2)
__device__ __forceinline__ float sel4n(float4 V, int j) {
    float a = (j & 1) ? V.z : V.y;   // j=0 -> y, j=1 -> z
    float b = V.w;                   // j=2 -> w
    return (j & 2) ? b : a;
}

// One branch, one pixel. img points at batch-n's [3,HW] plane set.
// y-tap pair (ify, icy) fetched via one aligned LDG.128 per row+channel,
// with a predicated scalar fallback when the pair crosses the 16B boundary.
__device__ __forceinline__ void sample_branch(const float* __restrict__ img,
                                              float qx0, float qy0, float m,
                                              float r[3],
                                              float& loss) {
    float qx = fminf(fmaxf(qx0, LO), HI);
    float qy = fminf(fmaxf(qy0, LO), HI);
    float dx = qx0 - qx;
    float dy = qy0 - qy;
    loss += dx * dx + dy * dy;

    float fx = floorf(qx);
    float fy = floorf(qy);
    float ax = qx - fx;              // in [0,1)
    float ay = qy - fy;

    int ifx = (int)fx, ify = (int)fy;
    int icx = ifx + (ax > 0.0f);     // == (int)ceilf(qx)
    int icy = ify + (ay > 0.0f);

    // weights: 1 - |q - nb|
    float wfx = 1.0f - ax;
    float wcx = 1.0f - ((float)icx - qx);
    float wfy = 1.0f - ay;
    float wcy = 1.0f - ((float)icy - qy);

    float wff = m * (wfx * wfy);     // img[fx][fy]
    float wcf = m * (wcx * wfy);     // img[cx][fy]
    float wfc = m * (wfx * wcy);     // img[fx][cy]
    float wcc = m * (wcx * wcy);     // img[cx][cy]

    int base4 = ify & ~3;            // 16B-aligned column group
    int j     = ify & 3;
    bool same_y  = (icy == ify);     // ay == 0 (exact-integer qy): duplicate tap
    bool need_fb = (!same_y) && (j == 3);   // pair crosses float4 boundary

    int rowf = ifx << 9;
    int rowc = icx << 9;

#pragma unroll
    for (int c = 0; c < 3; c++) {
        const float* ic = img + (size_t)c * HW;
        const float* rf = ic + rowf;
        const float* rc = ic + rowc;

        float4 Vf = __ldg((const float4*)(rf + base4));
        float4 Vc = __ldg((const float4*)(rc + base4));
        float fbf = need_fb ? __ldg(rf + icy) : 0.0f;   // predicated LDG
        float fbc = need_fb ? __ldg(rc + icy) : 0.0f;

        float v_f_fy = sel4(Vf, j);
        float v_c_fy = sel4(Vc, j);
        float v_f_cy = same_y ? v_f_fy : ((j == 3) ? fbf : sel4n(Vf, j));
        float v_c_cy = same_y ? v_c_fy : ((j == 3) ? fbc : sel4n(Vc, j));

        r[c] += wff * v_f_fy
              + wcf * v_c_fy
              + wfc * v_f_cy
              + wcc * v_c_cy;
    }
}

// Tile mapping: block = 16 rows (x) by 32 cols (y) of one batch image.
//   lane (0..31) -> y within tile (1 cache-line column)
//   warp (0..7)  -> 2 consecutive rows (x) via ILP-2
__global__ void __launch_bounds__(256) vm_main_kernel(
    const float* __restrict__ im1,
    const float* __restrict__ im2,
    const float* __restrict__ C,
    const float* __restrict__ M1,
    const float* __restrict__ M2,
    float* __restrict__ out) {

    int bid = blockIdx.x;
    int ty = (bid & 15) << 5;            // y-tile origin (16 tiles of 32)
    int tx = ((bid >> 4) & 31) << 4;     // x-tile origin (32 tiles of 16)
    int n  = bid >> 9;                   // batch

    int lane = threadIdx.x & 31;
    int w    = threadIdx.x >> 5;

    int y  = ty + lane;                  // column, fixed per thread
    int x0 = tx + (w << 1);              // first of 2 rows

    const float* Cn  = C  + (size_t)n * 2 * HW;
    const float* M1n = M1 + (size_t)n * HW;
    const float* M2n = M2 + (size_t)n * HW;
    const float* im1n = im1 + (size_t)n * 3 * HW;
    const float* im2n = im2 + (size_t)n * 3 * HW;
    float* outn = out + (size_t)n * 3 * HW;

    float yf = (float)y;
    float loss = 0.0f;

#pragma unroll
    for (int i = 0; i < 2; i++) {
        int x = x0 + i;
        int p = (x << 9) + y;
        float xf = (float)x;

        float c0 = __ldg(Cn + p);        // row-flow
        float c1 = __ldg(Cn + p + HW);   // col-flow
        float m1 = __ldg(M1n + p);
        float m2 = __ldg(M2n + p);

        float r[3] = {0.0f, 0.0f, 0.0f};
        // branch a: im1 sampled at q + C, masked by M1
        sample_branch(im1n, xf + c0, yf + c1, m1, r, loss);
        // branch b: im2 sampled at q - C, masked by M2
        sample_branch(im2n, xf - c0, yf - c1, m2, r, loss);

        outn[p]          = r[0];
        outn[p + HW]     = r[1];
        outn[p + 2 * HW] = r[2];
    }

    // ---- loss reduction: warp shfl -> smem -> per-block partial ----
#pragma unroll
    for (int off = 16; off > 0; off >>= 1)
        loss += __shfl_down_sync(0xFFFFFFFFu, loss, off);

    __shared__ float warp_part[8];
    if (lane == 0) warp_part[w] = loss;
    __syncthreads();
    if (threadIdx.x == 0) {
        float v = warp_part[0];
#pragma unroll
        for (int k = 1; k < 8; k++) v += warp_part[k];
        g_partials[bid] = v;
    }
}

__global__ void __launch_bounds__(1024) vm_finalize_kernel(float* __restrict__ out) {
    int t = threadIdx.x;
    const float4* p4 = (const float4*)g_partials;   // 4096 float4s
    float s = 0.0f;
#pragma unroll
    for (int i = 0; i < 4; i++) {
        float4 v = p4[t + i * 1024];
        s += (v.x + v.y) + (v.z + v.w);
    }
#pragma unroll
    for (int off = 16; off > 0; off >>= 1)
        s += __shfl_down_sync(0xFFFFFFFFu, s, off);
    __shared__ float warp_part[32];
    int w = t >> 5, lane = t & 31;
    if (lane == 0) warp_part[w] = s;
    __syncthreads();
    if (w == 0) {
        float v = warp_part[lane];
#pragma unroll
        for (int off = 16; off > 0; off >>= 1)
            v += __shfl_down_sync(0xFFFFFFFFu, v, off);
        if (lane == 0) {
            // la + lb = sum / (N*2*HW) / (D*D) * 0.01
            double denom = (double)NB * 2.0 * (double)HW;
            out[IMG_ELEMS] = (float)((double)v / denom * (0.01 / (double)(D * D)));
        }
    }
}

extern "C" void kernel_launch(void* const* d_in, const int* in_sizes, int n_in,
                              void* d_out, int out_size) {
    const float* im1 = (const float*)d_in[0];
    const float* im2 = (const float*)d_in[1];
    const float* C   = (const float*)d_in[2];
    const float* M1  = (const float*)d_in[3];
    const float* M2  = (const float*)d_in[4];
    float* out = (float*)d_out;

    vm_main_kernel<<<NBLOCKS, 256>>>(im1, im2, C, M1, M2, out);

    if ((size_t)out_size > IMG_ELEMS) {
        vm_finalize_kernel<<<1, 1024>>>(out);
    }
}

// round 11
// speedup vs baseline: 1.5542x; 1.5542x over previous
#include <cuda_runtime.h>
#include <cstdint>

#define D 512
#define HW (D * D)            // 262144 = 2^18
#define NB 32                 // batch
#define IMG_ELEMS ((size_t)NB * 3 * HW)
#define LO 0.001f
#define HI 510.999f           // D - 1.001
#define NBLOCKS 32768         // 32 batch * 64 x-tiles(8 rows) * 16 y-tiles(32 cols)

__device__ __align__(16) float g_partials[NBLOCKS];

// One branch, one pixel. img points at batch-n's [3,HW] plane set.
__device__ __forceinline__ void sample_branch(const float* __restrict__ img,
                                              float qx0, float qy0, float m,
                                              float r[3],
                                              float& loss) {
    float qx = fminf(fmaxf(qx0, LO), HI);
    float qy = fminf(fmaxf(qy0, LO), HI);
    float dx = qx0 - qx;
    float dy = qy0 - qy;
    loss += dx * dx + dy * dy;

    float fx = floorf(qx);
    float fy = floorf(qy);
    float ax = qx - fx;              // in [0,1)
    float ay = qy - fy;

    int ifx = (int)fx, ify = (int)fy;
    int icx = ifx + (ax > 0.0f);     // == (int)ceilf(qx)
    int icy = ify + (ay > 0.0f);

    // weights: 1 - |q - nb|
    float wfx = 1.0f - ax;
    float wcx = 1.0f - ((float)icx - qx);
    float wfy = 1.0f - ay;
    float wcy = 1.0f - ((float)icy - qy);

    // ind = y + D * x
    int i00 = ify + (ifx << 9);
    int i10 = ify + (icx << 9);
    int i01 = icy + (ifx << 9);
    int i11 = icy + (icx << 9);

    float wff = m * (wfx * wfy);
    float wcf = m * (wcx * wfy);
    float wfc = m * (wfx * wcy);
    float wcc = m * (wcx * wcy);

#pragma unroll
    for (int c = 0; c < 3; c++) {
        const float* ic = img + (size_t)c * HW;
        r[c] += wff * __ldg(ic + i00)
              + wcf * __ldg(ic + i10)
              + wfc * __ldg(ic + i01)
              + wcc * __ldg(ic + i11);
    }
}

// Tile mapping: block = 8 rows (x) by 32 cols (y) of one batch image.
//   lane (0..31) -> y within tile (1 cache-line column)
//   warp (0..7)  -> one row (ILP-1: minimal register pressure)
__global__ void __launch_bounds__(256) vm_main_kernel(
    const float* __restrict__ im1,
    const float* __restrict__ im2,
    const float* __restrict__ C,
    const float* __restrict__ M1,
    const float* __restrict__ M2,
    float* __restrict__ out) {

    int bid = blockIdx.x;
    int ty = (bid & 15) << 5;            // y-tile origin (16 tiles of 32)
    int tx = ((bid >> 4) & 63) << 3;     // x-tile origin (64 tiles of 8)
    int n  = bid >> 10;                  // batch

    int lane = threadIdx.x & 31;
    int w    = threadIdx.x >> 5;

    int y = ty + lane;                   // column
    int x = tx + w;                      // row
    int p = (x << 9) + y;

    const float* Cn  = C  + (size_t)n * 2 * HW;
    float c0 = __ldg(Cn + p);            // row-flow
    float c1 = __ldg(Cn + p + HW);       // col-flow
    float m1 = __ldg(M1 + (size_t)n * HW + p);
    float m2 = __ldg(M2 + (size_t)n * HW + p);

    float xf = (float)x;
    float yf = (float)y;
    float loss = 0.0f;

    float r[3] = {0.0f, 0.0f, 0.0f};
    const float* im1n = im1 + (size_t)n * 3 * HW;
    const float* im2n = im2 + (size_t)n * 3 * HW;

    // branch a: im1 sampled at q + C, masked by M1
    sample_branch(im1n, xf + c0, yf + c1, m1, r, loss);
    // branch b: im2 sampled at q - C, masked by M2
    sample_branch(im2n, xf - c0, yf - c1, m2, r, loss);

    float* outn = out + (size_t)n * 3 * HW;
    outn[p]          = r[0];
    outn[p + HW]     = r[1];
    outn[p + 2 * HW] = r[2];

    // ---- loss reduction: warp shfl -> smem -> per-block partial ----
#pragma unroll
    for (int off = 16; off > 0; off >>= 1)
        loss += __shfl_down_sync(0xFFFFFFFFu, loss, off);

    __shared__ float warp_part[8];
    if (lane == 0) warp_part[w] = loss;
    __syncthreads();
    if (threadIdx.x == 0) {
        float v = warp_part[0];
#pragma unroll
        for (int k = 1; k < 8; k++) v += warp_part[k];
        g_partials[bid] = v;
    }
}

__global__ void __launch_bounds__(1024) vm_finalize_kernel(float* __restrict__ out) {
    int t = threadIdx.x;
    const float4* p4 = (const float4*)g_partials;   // 8192 float4s
    float s = 0.0f;
#pragma unroll
    for (int i = 0; i < 8; i++) {
        float4 v = p4[t + i * 1024];
        s += (v.x + v.y) + (v.z + v.w);
    }
#pragma unroll
    for (int off = 16; off > 0; off >>= 1)
        s += __shfl_down_sync(0xFFFFFFFFu, s, off);
    __shared__ float warp_part[32];
    int w = t >> 5, lane = t & 31;
    if (lane == 0) warp_part[w] = s;
    __syncthreads();
    if (w == 0) {
        float v = warp_part[lane];
#pragma unroll
        for (int off = 16; off > 0; off >>= 1)
            v += __shfl_down_sync(0xFFFFFFFFu, v, off);
        if (lane == 0) {
            // la + lb = sum / (N*2*HW) / (D*D) * 0.01
            double denom = (double)NB * 2.0 * (double)HW;
            out[IMG_ELEMS] = (float)((double)v / denom * (0.01 / (double)(D * D)));
        }
    }
}

extern "C" void kernel_launch(void* const* d_in, const int* in_sizes, int n_in,
                              void* d_out, int out_size) {
    const float* im1 = (const float*)d_in[0];
    const float* im2 = (const float*)d_in[1];
    const float* C   = (const float*)d_in[2];
    const float* M1  = (const float*)d_in[3];
    const float* M2  = (const float*)d_in[4];
    float* out = (float*)d_out;

    vm_main_kernel<<<NBLOCKS, 256>>>(im1, im2, C, M1, M2, out);

    if ((size_t)out_size > IMG_ELEMS) {
        vm_finalize_kernel<<<1, 1024>>>(out);
    }
}

// round 12
// speedup vs baseline: 1.8321x; 1.1788x over previous
#include <cuda_runtime.h>
#include <cstdint>

#define D 512
#define HW (D * D)            // 262144 = 2^18
#define NB 32                 // batch
#define IMG_ELEMS ((size_t)NB * 3 * HW)
#define LO 0.001f
#define HI 510.999f           // D - 1.001
#define NBLOCKS 16384         // 32 batch * 32 x-tiles(16 rows) * 16 y-tiles(32 cols)

__device__ __align__(16) float g_partials[NBLOCKS];

// One branch, one pixel. img points at batch-n's [3,HW] plane set.
__device__ __forceinline__ void sample_branch(const float* __restrict__ img,
                                              float qx0, float qy0, float m,
                                              float r[3],
                                              float& loss) {
    float qx = fminf(fmaxf(qx0, LO), HI);
    float qy = fminf(fmaxf(qy0, LO), HI);
    float dx = qx0 - qx;
    float dy = qy0 - qy;
    loss += dx * dx + dy * dy;

    float fx = floorf(qx);
    float fy = floorf(qy);
    float ax = qx - fx;              // in [0,1)
    float ay = qy - fy;

    int ifx = (int)fx, ify = (int)fy;
    int icx = ifx + (ax > 0.0f);     // == (int)ceilf(qx)
    int icy = ify + (ay > 0.0f);

    // weights: 1 - |q - nb|
    float wfx = 1.0f - ax;
    float wcx = 1.0f - ((float)icx - qx);
    float wfy = 1.0f - ay;
    float wcy = 1.0f - ((float)icy - qy);

    // ind = y + D * x
    int i00 = ify + (ifx << 9);
    int i10 = ify + (icx << 9);
    int i01 = icy + (ifx << 9);
    int i11 = icy + (icx << 9);

    float wff = m * (wfx * wfy);
    float wcf = m * (wcx * wfy);
    float wfc = m * (wfx * wcy);
    float wcc = m * (wcx * wcy);

#pragma unroll
    for (int c = 0; c < 3; c++) {
        const float* ic = img + (size_t)c * HW;
        r[c] += wff * __ldg(ic + i00)
              + wcf * __ldg(ic + i10)
              + wfc * __ldg(ic + i01)
              + wcc * __ldg(ic + i11);
    }
}

// Tile mapping: block = 16 rows (x) by 32 cols (y) of one batch image.
//   lane (0..31) -> y within tile (1 cache-line column)
//   warp (0..7)  -> 2 consecutive rows (x) via ILP-2
__global__ void __launch_bounds__(256) vm_main_kernel(
    const float* __restrict__ im1,
    const float* __restrict__ im2,
    const float* __restrict__ C,
    const float* __restrict__ M1,
    const float* __restrict__ M2,
    float* __restrict__ out) {

    int bid = blockIdx.x;
    int ty = (bid & 15) << 5;            // y-tile origin (16 tiles of 32)
    int tx = ((bid >> 4) & 31) << 4;     // x-tile origin (32 tiles of 16)
    int n  = bid >> 9;                   // batch

    int lane = threadIdx.x & 31;
    int w    = threadIdx.x >> 5;

    int y  = ty + lane;                  // column, fixed per thread
    int x0 = tx + (w << 1);              // first of 2 rows

    const float* Cn  = C  + (size_t)n * 2 * HW;
    const float* M1n = M1 + (size_t)n * HW;
    const float* M2n = M2 + (size_t)n * HW;
    const float* im1n = im1 + (size_t)n * 3 * HW;
    const float* im2n = im2 + (size_t)n * 3 * HW;
    float* outn = out + (size_t)n * 3 * HW;

    float yf = (float)y;
    float loss = 0.0f;

#pragma unroll
    for (int i = 0; i < 2; i++) {
        int x = x0 + i;
        int p = (x << 9) + y;
        float xf = (float)x;

        // stream-once data: evict-first so image gather lines stay in L1
        float c0 = __ldcs(Cn + p);        // row-flow
        float c1 = __ldcs(Cn + p + HW);   // col-flow
        float m1 = __ldcs(M1n + p);
        float m2 = __ldcs(M2n + p);

        float r[3] = {0.0f, 0.0f, 0.0f};
        // branch a: im1 sampled at q + C, masked by M1
        sample_branch(im1n, xf + c0, yf + c1, m1, r, loss);
        // branch b: im2 sampled at q - C, masked by M2
        sample_branch(im2n, xf - c0, yf - c1, m2, r, loss);

        __stcs(outn + p,          r[0]);
        __stcs(outn + p + HW,     r[1]);
        __stcs(outn + p + 2 * HW, r[2]);
    }

    // ---- loss reduction: warp shfl -> smem -> per-block partial ----
#pragma unroll
    for (int off = 16; off > 0; off >>= 1)
        loss += __shfl_down_sync(0xFFFFFFFFu, loss, off);

    __shared__ float warp_part[8];
    if (lane == 0) warp_part[w] = loss;
    __syncthreads();
    if (threadIdx.x == 0) {
        float v = warp_part[0];
#pragma unroll
        for (int k = 1; k < 8; k++) v += warp_part[k];
        g_partials[bid] = v;
    }
}

__global__ void __launch_bounds__(1024) vm_finalize_kernel(float* __restrict__ out) {
    // PDL: we may have been launched before vm_main_kernel finished.
    // Wait for the upstream grid before touching g_partials.
#if __CUDA_ARCH__ >= 900
    cudaGridDependencySynchronize();
#endif
    int t = threadIdx.x;
    const float4* p4 = (const float4*)g_partials;   // 4096 float4s
    float s = 0.0f;
#pragma unroll
    for (int i = 0; i < 4; i++) {
        float4 v = p4[t + i * 1024];
        s += (v.x + v.y) + (v.z + v.w);
    }
#pragma unroll
    for (int off = 16; off > 0; off >>= 1)
        s += __shfl_down_sync(0xFFFFFFFFu, s, off);
    __shared__ float warp_part[32];
    int w = t >> 5, lane = t & 31;
    if (lane == 0) warp_part[w] = s;
    __syncthreads();
    if (w == 0) {
        float v = warp_part[lane];
#pragma unroll
        for (int off = 16; off > 0; off >>= 1)
            v += __shfl_down_sync(0xFFFFFFFFu, v, off);
        if (lane == 0) {
            // la + lb = sum / (N*2*HW) / (D*D) * 0.01
            double denom = (double)NB * 2.0 * (double)HW;
            out[IMG_ELEMS] = (float)((double)v / denom * (0.01 / (double)(D * D)));
        }
    }
}

extern "C" void kernel_launch(void* const* d_in, const int* in_sizes, int n_in,
                              void* d_out, int out_size) {
    const float* im1 = (const float*)d_in[0];
    const float* im2 = (const float*)d_in[1];
    const float* C   = (const float*)d_in[2];
    const float* M1  = (const float*)d_in[3];
    const float* M2  = (const float*)d_in[4];
    float* out = (float*)d_out;

    vm_main_kernel<<<NBLOCKS, 256>>>(im1, im2, C, M1, M2, out);

    if ((size_t)out_size > IMG_ELEMS) {
        // Programmatic dependent launch: overlap finalize launch latency with
        // the main kernel's drain; the device-side sync above provides ordering.
        cudaLaunchConfig_t cfg = {};
        cfg.gridDim  = dim3(1, 1, 1);
        cfg.blockDim = dim3(1024, 1, 1);
        cfg.dynamicSmemBytes = 0;
        cfg.stream = 0;
        cudaLaunchAttribute attr[1];
        attr[0].id = cudaLaunchAttributeProgrammaticStreamSerialization;
        attr[0].val.programmaticStreamSerializationAllowed = 1;
        cfg.attrs = attr;
        cfg.numAttrs = 1;
        cudaError_t e = cudaLaunchKernelEx(&cfg, vm_finalize_kernel, out);
        if (e != cudaSuccess) {
            // fallback: plain launch (still correct ordering on the stream)
            vm_finalize_kernel<<<1, 1024>>>(out);
        }
    }
}

// round 13
// speedup vs baseline: 1.8459x; 1.0075x over previous
#include <cuda_runtime.h>
#include <cstdint>

#define D 512
#define HW (D * D)            // 262144 = 2^18
#define NB 32                 // batch
#define IMG_ELEMS ((size_t)NB * 3 * HW)
#define LO 0.001f
#define HI 510.999f           // D - 1.001
#define NBLOCKS 8192          // 32 batch * 16 x-tiles(32 rows) * 16 y-tiles(32 cols)

__device__ __align__(16) float g_partials[NBLOCKS];

// One branch, one pixel. img points at batch-n's [3,HW] plane set.
__device__ __forceinline__ void sample_branch(const float* __restrict__ img,
                                              float qx0, float qy0, float m,
                                              float r[3],
                                              float& loss) {
    float qx = fminf(fmaxf(qx0, LO), HI);
    float qy = fminf(fmaxf(qy0, LO), HI);
    float dx = qx0 - qx;
    float dy = qy0 - qy;
    loss += dx * dx + dy * dy;

    float fx = floorf(qx);
    float fy = floorf(qy);
    float ax = qx - fx;              // in [0,1)
    float ay = qy - fy;

    int ifx = (int)fx, ify = (int)fy;
    int icx = ifx + (ax > 0.0f);     // == (int)ceilf(qx)
    int icy = ify + (ay > 0.0f);

    // weights: 1 - |q - nb|
    float wfx = 1.0f - ax;
    float wcx = 1.0f - ((float)icx - qx);
    float wfy = 1.0f - ay;
    float wcy = 1.0f - ((float)icy - qy);

    // ind = y + D * x
    int i00 = ify + (ifx << 9);
    int i10 = ify + (icx << 9);
    int i01 = icy + (ifx << 9);
    int i11 = icy + (icx << 9);

    float wff = m * (wfx * wfy);
    float wcf = m * (wcx * wfy);
    float wfc = m * (wfx * wcy);
    float wcc = m * (wcx * wcy);

#pragma unroll
    for (int c = 0; c < 3; c++) {
        const float* ic = img + (size_t)c * HW;
        r[c] += wff * __ldg(ic + i00)
              + wcf * __ldg(ic + i10)
              + wfc * __ldg(ic + i01)
              + wcc * __ldg(ic + i11);
    }
}

// Tile mapping: block = 32 rows (x) by 32 cols (y), 512 threads.
//   lane (0..31)  -> y within tile (1 cache-line column)
//   warp (0..15)  -> 2 consecutive rows (x) via ILP-2
__global__ void __launch_bounds__(512) vm_main_kernel(
    const float* __restrict__ im1,
    const float* __restrict__ im2,
    const float* __restrict__ C,
    const float* __restrict__ M1,
    const float* __restrict__ M2,
    float* __restrict__ out) {

    int bid = blockIdx.x;
    int ty = (bid & 15) << 5;            // y-tile origin (16 tiles of 32)
    int tx = ((bid >> 4) & 15) << 5;     // x-tile origin (16 tiles of 32)
    int n  = bid >> 8;                   // batch

    int lane = threadIdx.x & 31;
    int w    = threadIdx.x >> 5;

    int y  = ty + lane;                  // column, fixed per thread
    int x0 = tx + (w << 1);              // first of 2 rows

    const float* Cn  = C  + (size_t)n * 2 * HW;
    const float* M1n = M1 + (size_t)n * HW;
    const float* M2n = M2 + (size_t)n * HW;
    const float* im1n = im1 + (size_t)n * 3 * HW;
    const float* im2n = im2 + (size_t)n * 3 * HW;
    float* outn = out + (size_t)n * 3 * HW;

    float yf = (float)y;
    float loss = 0.0f;

    int p0 = (x0 << 9) + y;
    int p1 = p0 + D;

    // Front-batch all stream-once loads (evict-first) to maximize MLP.
    float c0a = __ldcs(Cn + p0);
    float c1a = __ldcs(Cn + p0 + HW);
    float m1a = __ldcs(M1n + p0);
    float m2a = __ldcs(M2n + p0);
    float c0b = __ldcs(Cn + p1);
    float c1b = __ldcs(Cn + p1 + HW);
    float m1b = __ldcs(M1n + p1);
    float m2b = __ldcs(M2n + p1);

    float xfa = (float)x0;
    float xfb = (float)(x0 + 1);

    float ra[3] = {0.0f, 0.0f, 0.0f};
    float rb[3] = {0.0f, 0.0f, 0.0f};

    // branch a: im1 sampled at q + C, masked by M1
    sample_branch(im1n, xfa + c0a, yf + c1a, m1a, ra, loss);
    // branch b: im2 sampled at q - C, masked by M2
    sample_branch(im2n, xfa - c0a, yf - c1a, m2a, ra, loss);

    sample_branch(im1n, xfb + c0b, yf + c1b, m1b, rb, loss);
    sample_branch(im2n, xfb - c0b, yf - c1b, m2b, rb, loss);

    __stcs(outn + p0,          ra[0]);
    __stcs(outn + p0 + HW,     ra[1]);
    __stcs(outn + p0 + 2 * HW, ra[2]);
    __stcs(outn + p1,          rb[0]);
    __stcs(outn + p1 + HW,     rb[1]);
    __stcs(outn + p1 + 2 * HW, rb[2]);

    // ---- loss reduction: warp shfl -> smem -> per-block partial ----
#pragma unroll
    for (int off = 16; off > 0; off >>= 1)
        loss += __shfl_down_sync(0xFFFFFFFFu, loss, off);

    __shared__ float warp_part[16];
    if (lane == 0) warp_part[w] = loss;
    __syncthreads();
    if (threadIdx.x == 0) {
        float v = warp_part[0];
#pragma unroll
        for (int k = 1; k < 16; k++) v += warp_part[k];
        g_partials[bid] = v;
    }
}

__global__ void __launch_bounds__(1024) vm_finalize_kernel(float* __restrict__ out) {
    // PDL: wait for the upstream grid before touching g_partials.
#if __CUDA_ARCH__ >= 900
    cudaGridDependencySynchronize();
#endif
    int t = threadIdx.x;
    const float4* p4 = (const float4*)g_partials;   // 2048 float4s
    float s = 0.0f;
#pragma unroll
    for (int i = 0; i < 2; i++) {
        float4 v = p4[t + i * 1024];
        s += (v.x + v.y) + (v.z + v.w);
    }
#pragma unroll
    for (int off = 16; off > 0; off >>= 1)
        s += __shfl_down_sync(0xFFFFFFFFu, s, off);
    __shared__ float warp_part[32];
    int w = t >> 5, lane = t & 31;
    if (lane == 0) warp_part[w] = s;
    __syncthreads();
    if (w == 0) {
        float v = warp_part[lane];
#pragma unroll
        for (int off = 16; off > 0; off >>= 1)
            v += __shfl_down_sync(0xFFFFFFFFu, v, off);
        if (lane == 0) {
            // la + lb = sum / (N*2*HW) / (D*D) * 0.01
            double denom = (double)NB * 2.0 * (double)HW;
            out[IMG_ELEMS] = (float)((double)v / denom * (0.01 / (double)(D * D)));
        }
    }
}

extern "C" void kernel_launch(void* const* d_in, const int* in_sizes, int n_in,
                              void* d_out, int out_size) {
    const float* im1 = (const float*)d_in[0];
    const float* im2 = (const float*)d_in[1];
    const float* C   = (const float*)d_in[2];
    const float* M1  = (const float*)d_in[3];
    const float* M2  = (const float*)d_in[4];
    float* out = (float*)d_out;

    vm_main_kernel<<<NBLOCKS, 512>>>(im1, im2, C, M1, M2, out);

    if ((size_t)out_size > IMG_ELEMS) {
        // Programmatic dependent launch: overlap finalize launch latency with
        // the main kernel's drain; device-side sync provides ordering.
        cudaLaunchConfig_t cfg = {};
        cfg.gridDim  = dim3(1, 1, 1);
        cfg.blockDim = dim3(1024, 1, 1);
        cfg.dynamicSmemBytes = 0;
        cfg.stream = 0;
        cudaLaunchAttribute attr[1];
        attr[0].id = cudaLaunchAttributeProgrammaticStreamSerialization;
        attr[0].val.programmaticStreamSerializationAllowed = 1;
        cfg.attrs = attr;
        cfg.numAttrs = 1;
        cudaError_t e = cudaLaunchKernelEx(&cfg, vm_finalize_kernel, out);
        if (e != cudaSuccess) {
            vm_finalize_kernel<<<1, 1024>>>(out);
        }
    }
}